// round 15
// baseline (speedup 1.0000x reference)
#include <cuda_runtime.h>
#include <cuda_fp16.h>
#include <math.h>
#include <stdint.h>

#define NH 16
#define HD 128
#define TSEQ 2048
#define BB 2
#define DM 2048
#define NTOK (BB * TSEQ)          // 4096
#define QKV_COLS (3 * DM)         // 6144

// ---------------- scratch (device globals: no allocation allowed) ------------
__device__ float g_cos[TSEQ * (HD / 2)];
__device__ float g_sin[TSEQ * (HD / 2)];
// fp16 operands for projections (all hi-only)
__device__ __half g_xh[(size_t)NTOK * DM];
__device__ __half g_wqkvh[(size_t)QKV_COLS * DM];
__device__ __half g_woh[(size_t)DM * DM];
__device__ __half g_ch[(size_t)NTOK * DM];    // attention output, fp16
// attention operands (fp16 hi only). q/k: [BH][T][HD]; vt: [BH][HD][T]
#define BH_T_HD ((size_t)BB * NH * TSEQ * HD)
__device__ __half g_qh[BH_T_HD];
__device__ __half g_kh[BH_T_HD];
__device__ __half g_vth[BH_T_HD];

// ---------------- helpers ------------------------------------------------------
__device__ __forceinline__ uint32_t smem_u32(const void* p) {
    uint32_t a;
    asm("{ .reg .u64 t; cvta.to.shared.u64 t, %1; cvt.u32.u64 %0, t; }"
        : "=r"(a) : "l"(p));
    return a;
}
__device__ __forceinline__ void cpa16(uint32_t dst, const void* src) {
    asm volatile("cp.async.cg.shared.global [%0], [%1], 16;" :: "r"(dst), "l"(src));
}
__device__ __forceinline__ void ldm_x4(uint32_t* r, uint32_t addr) {
    asm volatile("ldmatrix.sync.aligned.m8n8.x4.shared.b16 {%0,%1,%2,%3}, [%4];"
                 : "=r"(r[0]), "=r"(r[1]), "=r"(r[2]), "=r"(r[3]) : "r"(addr));
}
__device__ __forceinline__ void mma16816h(float* d, const uint32_t* a, uint32_t b0, uint32_t b1) {
    asm volatile(
        "mma.sync.aligned.m16n8k16.row.col.f32.f16.f16.f32 "
        "{%0,%1,%2,%3}, {%4,%5,%6,%7}, {%8,%9}, {%0,%1,%2,%3};"
        : "+f"(d[0]), "+f"(d[1]), "+f"(d[2]), "+f"(d[3])
        : "r"(a[0]), "r"(a[1]), "r"(a[2]), "r"(a[3]), "r"(b0), "r"(b1));
}
__device__ __forceinline__ uint32_t packh(float p0, float p1) {
    uint32_t r;
    asm("cvt.rn.f16x2.f32 %0, %1, %2;" : "=r"(r) : "f"(p1), "f"(p0));
    return r;
}

// ---------------- RoPE table ----------------------------------------------------
__global__ void rope_table_kernel() {
    int idx = blockIdx.x * blockDim.x + threadIdx.x;
    if (idx >= TSEQ * (HD / 2)) return;
    int t = idx / (HD / 2);
    int i = idx % (HD / 2);
    double inv = exp(-log(10000.0) * (double)(2 * i) / (double)HD);
    double ang = (double)t * inv;
    g_cos[idx] = (float)cos(ang);
    g_sin[idx] = (float)sin(ang);
}

// ---------------- fp32 -> fp16 convert -------------------------------------------
__global__ void convert_hi_fp16(const float2* __restrict__ s, __half2* __restrict__ hi, int n2) {
    int i = blockIdx.x * 256 + threadIdx.x;
    if (i >= n2) return;
    float2 v = s[i];
    hi[i] = __floats2half2_rn(v.x, v.y);
}

// ---------------- GEMM tiles / smem ----------------------------------------------
#define GROW 72                           // padded smem row (fp16 elems)
#define GTILE_B (128 * GROW * 2)          // 18432 bytes
#define GSTAGE_B (2 * GTILE_B)            // 36864 bytes (Ah, Bh)
#define G_SMEM_TOTAL (2 * GSTAGE_B)       // 73728 bytes (>= 128*133*4 epilogue tile)
#define ESTR 133                          // fp32 epilogue stage stride

__device__ __forceinline__ void ld_tile64(uint32_t dst, const __half* g, int ldK) {
#pragma unroll
    for (int r = 0; r < 4; r++) {
        int idx = threadIdx.x + r * 256;
        int row = idx >> 3, c = idx & 7;
        cpa16(dst + (row * GROW + c * 8) * 2, g + (size_t)row * ldK + c * 8);
    }
}

// mainloop shared by both GEMMs: leaves acc[4][4][4] accumulated
#define GEMM_MAINLOOP(Ap, Bh, K)                                                   \
    int nc = (K) / 64;                                                             \
    _Pragma("unroll")                                                              \
    for (int s = 0; s < 2; s++) {                                                  \
        uint32_t st = sb + s * GSTAGE_B;                                           \
        ld_tile64(st + 0 * GTILE_B, (Ap) + s * 64, (K));                           \
        ld_tile64(st + 1 * GTILE_B, (Bh) + s * 64, (K));                           \
        asm volatile("cp.async.commit_group;" ::: "memory");                       \
    }                                                                              \
    int lrow = lane & 15;                                                          \
    int lcol8 = (lane >> 4) * 8;                                                   \
    for (int i = 0; i < nc; i++) {                                                 \
        if (i == nc - 1) asm volatile("cp.async.wait_group 0;" ::: "memory");      \
        else             asm volatile("cp.async.wait_group 1;" ::: "memory");      \
        __syncthreads();                                                           \
        uint32_t st = sb + (uint32_t)(i & 1) * GSTAGE_B;                           \
        uint32_t sA = st, sBh = st + GTILE_B;                                      \
        _Pragma("unroll")                                                          \
        for (int ks = 0; ks < 4; ks++) {                                           \
            int kc = ks * 16 + lcol8;                                              \
            uint32_t a[4][4], bhf[2][4];                                           \
            _Pragma("unroll")                                                      \
            for (int mi = 0; mi < 4; mi++) {                                       \
                int r = wm * 64 + mi * 16 + lrow;                                  \
                ldm_x4(a[mi], sA + (r * GROW + kc) * 2);                           \
            }                                                                      \
            _Pragma("unroll")                                                      \
            for (int nb = 0; nb < 2; nb++) {                                       \
                int r = wn * 32 + nb * 16 + lrow;                                  \
                ldm_x4(bhf[nb], sBh + (r * GROW + kc) * 2);                        \
            }                                                                      \
            _Pragma("unroll")                                                      \
            for (int mi = 0; mi < 4; mi++)                                         \
                _Pragma("unroll")                                                  \
                for (int nb = 0; nb < 2; nb++) {                                   \
                    mma16816h(acc[mi][2 * nb + 0], a[mi], bhf[nb][0], bhf[nb][2]); \
                    mma16816h(acc[mi][2 * nb + 1], a[mi], bhf[nb][1], bhf[nb][3]); \
                }                                                                  \
        }                                                                          \
        __syncthreads();                                                           \
        if (i + 2 < nc) {                                                          \
            int k0 = (i + 2) * 64;                                                 \
            ld_tile64(st + 0 * GTILE_B, (Ap) + k0, (K));                           \
            ld_tile64(st + 1 * GTILE_B, (Bh) + k0, (K));                           \
            asm volatile("cp.async.commit_group;" ::: "memory");                   \
        }                                                                          \
    }

// ---------------- QKV GEMM with fused RoPE/head-split/V-transpose epilogue -------
__global__ void __launch_bounds__(256, 2)
gemm_qkv_rope(const __half* __restrict__ Ah, const __half* __restrict__ Bhi,
              const float* __restrict__ bias) {
    extern __shared__ __align__(128) char sm[];
    uint32_t sb = smem_u32(sm);
    int tid = threadIdx.x, wid = tid >> 5, lane = tid & 31;
    int wm = wid & 1, wn = wid >> 1;
    int bm = blockIdx.y * 128, bn = blockIdx.x * 128;

    const __half* Ap = Ah  + (size_t)bm * 2048;
    const __half* Bh = Bhi + (size_t)bn * 2048;

    float acc[4][4][4];
#pragma unroll
    for (int i = 0; i < 4; i++)
#pragma unroll
        for (int j = 0; j < 4; j++)
#pragma unroll
            for (int k = 0; k < 4; k++) acc[i][j][k] = 0.f;

    GEMM_MAINLOOP(Ap, Bh, 2048)

    // ---- stage acc(+bias) into fp32 smem tile [128][ESTR] ----
    float* S = (float*)sm;
    int qrow = lane >> 2, qcol = (lane & 3) * 2;
#pragma unroll
    for (int mi = 0; mi < 4; mi++) {
#pragma unroll
        for (int ni = 0; ni < 4; ni++) {
            int cl = wn * 32 + ni * 8 + qcol;
            float b0 = bias[bn + cl], b1 = bias[bn + cl + 1];
            int rl = wm * 64 + mi * 16 + qrow;
            S[rl * ESTR + cl]           = acc[mi][ni][0] + b0;
            S[rl * ESTR + cl + 1]       = acc[mi][ni][1] + b1;
            S[(rl + 8) * ESTR + cl]     = acc[mi][ni][2] + b0;
            S[(rl + 8) * ESTR + cl + 1] = acc[mi][ni][3] + b1;
        }
    }
    __syncthreads();

    int type = blockIdx.x >> 4;       // 0=q, 1=k, 2=v
    int head = blockIdx.x & 15;
    int b = bm >> 11;                 // token block is within one batch (128 | 2048)
    int t0 = bm & (TSEQ - 1);

    if (type == 2) {
        // V: transposed write [bh][d][t], t contiguous
        int d = tid & 127;
        int th = (tid >> 7) * 64;
        int bh = b * NH + head;
        __half* dst = g_vth + ((size_t)bh * HD + d) * TSEQ + t0 + th;
#pragma unroll
        for (int chunk = 0; chunk < 4; chunk++) {
            uint32_t buf[8];
#pragma unroll
            for (int j = 0; j < 8; j++) {
                int tt = th + chunk * 16 + j * 2;
                buf[j] = packh(S[tt * ESTR + d], S[(tt + 1) * ESTR + d]);
            }
            // 16 halves = 32 bytes contiguous in t
            *(uint4*)((__half*)dst + chunk * 16)     = *(uint4*)(buf);
            *(uint4*)((__half*)dst + chunk * 16 + 8) = *(uint4*)(buf + 4);
        }
    } else {
        // Q/K: RoPE + write [bh][t][hd]
        int rl = tid >> 1;
        int dd0 = (tid & 1) * 32;
        int t = t0 + rl;
        int bh = b * NH + head;
        float scale = (type == 0) ? 0.08838834764831845f : 1.0f;
        __half* dst = (type == 0 ? g_qh : g_kh) + ((size_t)bh * TSEQ + t) * HD;
#pragma unroll
        for (int chunk = 0; chunk < 4; chunk++) {
            uint32_t b1[4], b2[4];
#pragma unroll
            for (int j = 0; j < 4; j++) {
                int dd = dd0 + chunk * 8 + j * 2;
                float c0 = g_cos[t * 64 + dd],     s0 = g_sin[t * 64 + dd];
                float c1 = g_cos[t * 64 + dd + 1], s1 = g_sin[t * 64 + dd + 1];
                float x10 = S[rl * ESTR + dd],      x20 = S[rl * ESTR + dd + 64];
                float x11 = S[rl * ESTR + dd + 1],  x21 = S[rl * ESTR + dd + 65];
                b1[j] = packh((x10 * c0 - x20 * s0) * scale, (x11 * c1 - x21 * s1) * scale);
                b2[j] = packh((x10 * s0 + x20 * c0) * scale, (x11 * s1 + x21 * c1) * scale);
            }
            *(uint4*)(dst + dd0 + chunk * 8)      = *(uint4*)(b1);
            *(uint4*)(dst + 64 + dd0 + chunk * 8) = *(uint4*)(b2);
        }
    }
}

// ---------------- plain GEMM (fp32 out + bias) for the output projection ---------
__global__ void __launch_bounds__(256, 2)
gemm_fp16_1t(const __half* __restrict__ Ah, const __half* __restrict__ Bhi,
             const float* __restrict__ bias, float* __restrict__ C,
             int M, int N, int K) {
    extern __shared__ __align__(128) char sm[];
    uint32_t sb = smem_u32(sm);
    int tid = threadIdx.x, wid = tid >> 5, lane = tid & 31;
    int wm = wid & 1, wn = wid >> 1;
    int bm = blockIdx.y * 128, bn = blockIdx.x * 128;

    const __half* Ap = Ah  + (size_t)bm * K;
    const __half* Bh = Bhi + (size_t)bn * K;

    float acc[4][4][4];
#pragma unroll
    for (int i = 0; i < 4; i++)
#pragma unroll
        for (int j = 0; j < 4; j++)
#pragma unroll
            for (int k = 0; k < 4; k++) acc[i][j][k] = 0.f;

    GEMM_MAINLOOP(Ap, Bh, K)

    int qrow = lane >> 2, qcol = (lane & 3) * 2;
#pragma unroll
    for (int mi = 0; mi < 4; mi++) {
#pragma unroll
        for (int ni = 0; ni < 4; ni++) {
            int c = bn + wn * 32 + ni * 8 + qcol;
            float b0 = bias[c], b1 = bias[c + 1];
            int r0 = bm + wm * 64 + mi * 16 + qrow;
            *(float2*)(C + (size_t)r0 * N + c) =
                make_float2(acc[mi][ni][0] + b0, acc[mi][ni][1] + b1);
            *(float2*)(C + (size_t)(r0 + 8) * N + c) =
                make_float2(acc[mi][ni][2] + b0, acc[mi][ni][3] + b1);
        }
    }
}

// ---------------- HMMA flash attention (causal), fp16, P hi-only PV --------------
#define ABM 128
#define ABN 64
#define QSTR 136
#define KSTR 136
#define VSTR 72
#define KV_KH_B (ABN * KSTR * 2)                // 17408
#define KV_V_B  (HD * VSTR * 2)                 // 18432
#define KV_STAGE_B (KV_KH_B + KV_V_B)           // 35840
#define SM_Q  0
#define SM_KV (ABM * QSTR * 2)                  // 34816
#define ATT_SMEM (SM_KV + 2 * KV_STAGE_B)       // 106496  -> 2 CTAs/SM

__device__ __forceinline__ void ld_kv(uint32_t stage_base, int bh, int kb) {
    const __half* Kh = g_kh + ((size_t)bh * TSEQ + kb * ABN) * HD;
#pragma unroll
    for (int i = 0; i < 4; i++) {
        int idx = threadIdx.x + i * 256;
        int row = idx >> 4, c = idx & 15;
        cpa16(stage_base + (row * KSTR + c * 8) * 2, Kh + (size_t)row * HD + c * 8);
    }
    const __half* V = g_vth + (size_t)bh * HD * TSEQ + kb * ABN;
#pragma unroll
    for (int i = 0; i < 4; i++) {
        int idx = threadIdx.x + i * 256;
        int row = idx >> 3, c = idx & 7;
        cpa16(stage_base + KV_KH_B + (row * VSTR + c * 8) * 2, V + (size_t)row * TSEQ + c * 8);
    }
    asm volatile("cp.async.commit_group;" ::: "memory");
}

__global__ void __launch_bounds__(256, 2)
attn_mma_kernel() {
    extern __shared__ __align__(128) char smA[];
    uint32_t sb = smem_u32(smA);
    int tid = threadIdx.x, wid = tid >> 5, lane = tid & 31;
    int qb = (gridDim.x - 1) - blockIdx.x;      // heavy CTAs launch first
    int bh = blockIdx.y;
    int lrow = lane & 15;
    int lcol8 = (lane >> 4) * 8;
    int qrow = lane >> 2, qcol = (lane & 3) * 2;
    int nkb = 2 * qb + 2;

    // ---- prologue: Q, KV0, KV1 ----
    {
        const __half* Q = g_qh + ((size_t)bh * TSEQ + qb * ABM) * HD;
#pragma unroll
        for (int i = 0; i < 8; i++) {
            int idx = tid + i * 256;
            int row = idx >> 4, c = idx & 15;
            cpa16(sb + SM_Q + (row * QSTR + c * 8) * 2, Q + (size_t)row * HD + c * 8);
        }
        asm volatile("cp.async.commit_group;" ::: "memory");
    }
    ld_kv(sb + SM_KV, bh, 0);
    if (nkb > 1) ld_kv(sb + SM_KV + KV_STAGE_B, bh, 1);

    float o[16][4];
#pragma unroll
    for (int i = 0; i < 16; i++)
#pragma unroll
        for (int j = 0; j < 4; j++) o[i][j] = 0.f;
    float m0 = -1e30f, m1 = -1e30f, l0 = 0.f, l1 = 0.f;

    for (int kb = 0; kb < nkb; kb++) {
        if (kb + 1 < nkb) asm volatile("cp.async.wait_group 1;" ::: "memory");
        else              asm volatile("cp.async.wait_group 0;" ::: "memory");
        __syncthreads();

        uint32_t skv = sb + SM_KV + (uint32_t)(kb & 1) * KV_STAGE_B;
        uint32_t sKH = skv, sV = skv + KV_KH_B;

        // ---- S = Q K^T ----
        float s[8][4];
#pragma unroll
        for (int i = 0; i < 8; i++)
#pragma unroll
            for (int j = 0; j < 4; j++) s[i][j] = 0.f;
#pragma unroll
        for (int kc = 0; kc < 8; kc++) {
            uint32_t a[4];
            ldm_x4(a, sb + SM_Q + ((wid * 16 + lrow) * QSTR + kc * 16 + lcol8) * 2);
#pragma unroll
            for (int nb = 0; nb < 4; nb++) {
                uint32_t bhh[4];
                ldm_x4(bhh, sKH + ((nb * 16 + lrow) * KSTR + kc * 16 + lcol8) * 2);
                mma16816h(s[2 * nb + 0], a, bhh[0], bhh[2]);
                mma16816h(s[2 * nb + 1], a, bhh[1], bhh[3]);
            }
        }

        // ---- causal mask ----
        if (kb >= 2 * qb) {
            int rg = qb * ABM + wid * 16 + qrow;
#pragma unroll
            for (int nb = 0; nb < 8; nb++) {
#pragma unroll
                for (int e = 0; e < 2; e++) {
                    int col = kb * ABN + nb * 8 + qcol + e;
                    if (col > rg)     s[nb][e]     = -1e30f;
                    if (col > rg + 8) s[nb][2 + e] = -1e30f;
                }
            }
        }

        // ---- online softmax ----
        float mx0 = -1e30f, mx1 = -1e30f;
#pragma unroll
        for (int nb = 0; nb < 8; nb++) {
            mx0 = fmaxf(mx0, fmaxf(s[nb][0], s[nb][1]));
            mx1 = fmaxf(mx1, fmaxf(s[nb][2], s[nb][3]));
        }
        mx0 = fmaxf(mx0, __shfl_xor_sync(0xffffffffu, mx0, 1));
        mx0 = fmaxf(mx0, __shfl_xor_sync(0xffffffffu, mx0, 2));
        mx1 = fmaxf(mx1, __shfl_xor_sync(0xffffffffu, mx1, 1));
        mx1 = fmaxf(mx1, __shfl_xor_sync(0xffffffffu, mx1, 2));
        float mn0 = fmaxf(m0, mx0), mn1 = fmaxf(m1, mx1);
        float a0 = __expf(m0 - mn0), a1 = __expf(m1 - mn1);
        float sum0 = 0.f, sum1 = 0.f;
#pragma unroll
        for (int nb = 0; nb < 8; nb++) {
            s[nb][0] = __expf(s[nb][0] - mn0); sum0 += s[nb][0];
            s[nb][1] = __expf(s[nb][1] - mn0); sum0 += s[nb][1];
            s[nb][2] = __expf(s[nb][2] - mn1); sum1 += s[nb][2];
            s[nb][3] = __expf(s[nb][3] - mn1); sum1 += s[nb][3];
        }
        sum0 += __shfl_xor_sync(0xffffffffu, sum0, 1);
        sum0 += __shfl_xor_sync(0xffffffffu, sum0, 2);
        sum1 += __shfl_xor_sync(0xffffffffu, sum1, 1);
        sum1 += __shfl_xor_sync(0xffffffffu, sum1, 2);
        l0 = l0 * a0 + sum0; l1 = l1 * a1 + sum1;
        m0 = mn0; m1 = mn1;
#pragma unroll
        for (int nb = 0; nb < 16; nb++) {
            o[nb][0] *= a0; o[nb][1] *= a0;
            o[nb][2] *= a1; o[nb][3] *= a1;
        }

        // ---- O += P @ V (P hi-only fp16, V hi-only) ----
#pragma unroll
        for (int kk = 0; kk < 4; kk++) {
            uint32_t pah[4];
            pah[0] = packh(s[2 * kk][0],     s[2 * kk][1]);
            pah[1] = packh(s[2 * kk][2],     s[2 * kk][3]);
            pah[2] = packh(s[2 * kk + 1][0], s[2 * kk + 1][1]);
            pah[3] = packh(s[2 * kk + 1][2], s[2 * kk + 1][3]);
#pragma unroll
            for (int blk = 0; blk < 8; blk++) {
                uint32_t vb[4];
                ldm_x4(vb, sV + ((blk * 16 + lrow) * VSTR + kk * 16 + lcol8) * 2);
                mma16816h(o[2 * blk + 0], pah, vb[0], vb[2]);
                mma16816h(o[2 * blk + 1], pah, vb[1], vb[3]);
            }
        }
        __syncthreads();

        if (kb + 2 < nkb) ld_kv(sb + SM_KV + (uint32_t)(kb & 1) * KV_STAGE_B, bh, kb + 2);
    }

    // ---- epilogue: normalize and write ctx directly as fp16 ----
    float inv0 = 1.0f / l0, inv1 = 1.0f / l1;
    int b = bh >> 4, h = bh & 15;
    int r0 = qb * ABM + wid * 16 + qrow;
    __half* base0 = g_ch + ((size_t)(b * TSEQ + r0)) * DM + h * HD + qcol;
    __half* base1 = g_ch + ((size_t)(b * TSEQ + r0 + 8)) * DM + h * HD + qcol;
#pragma unroll
    for (int nb = 0; nb < 16; nb++) {
        *(uint32_t*)(base0 + nb * 8) = packh(o[nb][0] * inv0, o[nb][1] * inv0);
        *(uint32_t*)(base1 + nb * 8) = packh(o[nb][2] * inv1, o[nb][3] * inv1);
    }
}

// ---------------- launcher --------------------------------------------------------
extern "C" void kernel_launch(void* const* d_in, const int* in_sizes, int n_in,
                              void* d_out, int out_size) {
    const float* x    = (const float*)d_in[0];
    const float* Wqkv = (const float*)d_in[1];
    const float* bqkv = (const float*)d_in[2];
    const float* Wo   = (const float*)d_in[3];
    const float* bo   = (const float*)d_in[4];
    float* out = (float*)d_out;

    __half *xh, *wqh, *woh, *ch;
    cudaGetSymbolAddress((void**)&xh, g_xh);
    cudaGetSymbolAddress((void**)&wqh, g_wqkvh);
    cudaGetSymbolAddress((void**)&woh, g_woh);
    cudaGetSymbolAddress((void**)&ch, g_ch);

    cudaFuncSetAttribute(gemm_qkv_rope,
                         cudaFuncAttributeMaxDynamicSharedMemorySize, G_SMEM_TOTAL);
    cudaFuncSetAttribute(gemm_fp16_1t,
                         cudaFuncAttributeMaxDynamicSharedMemorySize, G_SMEM_TOTAL);
    cudaFuncSetAttribute(attn_mma_kernel,
                         cudaFuncAttributeMaxDynamicSharedMemorySize, ATT_SMEM);

    // 1) RoPE table (needed by QKV GEMM epilogue)
    rope_table_kernel<<<(TSEQ * (HD / 2) + 255) / 256, 256>>>();

    // 2) converts: x, Wqkv -> fp16 hi
    {
        int n2 = (NTOK * DM) / 2;
        convert_hi_fp16<<<(n2 + 255) / 256, 256>>>((const float2*)x, (__half2*)xh, n2);
        n2 = (QKV_COLS * DM) / 2;
        convert_hi_fp16<<<(n2 + 255) / 256, 256>>>((const float2*)Wqkv, (__half2*)wqh, n2);
    }

    // 3) QKV projection with fused RoPE + head split + V transpose
    {
        dim3 grid(QKV_COLS / 128, NTOK / 128);
        gemm_qkv_rope<<<grid, 256, G_SMEM_TOTAL>>>(xh, wqh, bqkv);
    }

    // 4) causal flash attention (fp16, P hi-only PV, fused fp16 ctx epilogue)
    {
        dim3 grid(TSEQ / ABM, BB * NH);
        attn_mma_kernel<<<grid, 256, ATT_SMEM>>>();
    }

    // 5) convert: Wo -> fp16 hi
    {
        int n2 = (DM * DM) / 2;
        convert_hi_fp16<<<(n2 + 255) / 256, 256>>>((const float2*)Wo, (__half2*)woh, n2);
    }

    // 6) output projection (fp16 HMMA, fp32 output)
    {
        dim3 grid(DM / 128, NTOK / 128);
        gemm_fp16_1t<<<grid, 256, G_SMEM_TOTAL>>>(ch, woh, bo, out, NTOK, DM, DM);
    }
}

// round 16
// speedup vs baseline: 1.0517x; 1.0517x over previous
#include <cuda_runtime.h>
#include <cuda_fp16.h>
#include <math.h>
#include <stdint.h>

#define NH 16
#define HD 128
#define TSEQ 2048
#define BB 2
#define DM 2048
#define NTOK (BB * TSEQ)          // 4096
#define QKV_COLS (3 * DM)         // 6144

// ---------------- scratch (device globals: no allocation allowed) ------------
__device__ __half g_qkvh[(size_t)NTOK * QKV_COLS];   // fp16 qkv (GEMM output; V read in-place)
__device__ float g_cos[TSEQ * (HD / 2)];
__device__ float g_sin[TSEQ * (HD / 2)];
__device__ __half g_xh[(size_t)NTOK * DM];
__device__ __half g_wqkvh[(size_t)QKV_COLS * DM];
__device__ __half g_woh[(size_t)DM * DM];
__device__ __half g_ch[(size_t)NTOK * DM];    // attention output, fp16
// attention q/k (fp16, RoPE'd): [BH][T][HD]
#define BH_T_HD ((size_t)BB * NH * TSEQ * HD)
__device__ __half g_qh[BH_T_HD];
__device__ __half g_kh[BH_T_HD];

// ---------------- helpers ------------------------------------------------------
__device__ __forceinline__ uint32_t smem_u32(const void* p) {
    uint32_t a;
    asm("{ .reg .u64 t; cvta.to.shared.u64 t, %1; cvt.u32.u64 %0, t; }"
        : "=r"(a) : "l"(p));
    return a;
}
__device__ __forceinline__ void cpa16(uint32_t dst, const void* src) {
    asm volatile("cp.async.cg.shared.global [%0], [%1], 16;" :: "r"(dst), "l"(src));
}
__device__ __forceinline__ void ldm_x4(uint32_t* r, uint32_t addr) {
    asm volatile("ldmatrix.sync.aligned.m8n8.x4.shared.b16 {%0,%1,%2,%3}, [%4];"
                 : "=r"(r[0]), "=r"(r[1]), "=r"(r[2]), "=r"(r[3]) : "r"(addr));
}
__device__ __forceinline__ void ldm_x4t(uint32_t* r, uint32_t addr) {
    asm volatile("ldmatrix.sync.aligned.m8n8.x4.trans.shared.b16 {%0,%1,%2,%3}, [%4];"
                 : "=r"(r[0]), "=r"(r[1]), "=r"(r[2]), "=r"(r[3]) : "r"(addr));
}
__device__ __forceinline__ void mma16816h(float* d, const uint32_t* a, uint32_t b0, uint32_t b1) {
    asm volatile(
        "mma.sync.aligned.m16n8k16.row.col.f32.f16.f16.f32 "
        "{%0,%1,%2,%3}, {%4,%5,%6,%7}, {%8,%9}, {%0,%1,%2,%3};"
        : "+f"(d[0]), "+f"(d[1]), "+f"(d[2]), "+f"(d[3])
        : "r"(a[0]), "r"(a[1]), "r"(a[2]), "r"(a[3]), "r"(b0), "r"(b1));
}
__device__ __forceinline__ uint32_t packh(float p0, float p1) {
    uint32_t r;
    asm("cvt.rn.f16x2.f32 %0, %1, %2;" : "=r"(r) : "f"(p1), "f"(p0));
    return r;
}

// ---------------- RoPE table ----------------------------------------------------
__global__ void rope_table_kernel() {
    int idx = blockIdx.x * blockDim.x + threadIdx.x;
    if (idx >= TSEQ * (HD / 2)) return;
    int t = idx / (HD / 2);
    int i = idx % (HD / 2);
    double inv = exp(-log(10000.0) * (double)(2 * i) / (double)HD);
    double ang = (double)t * inv;
    g_cos[idx] = (float)cos(ang);
    g_sin[idx] = (float)sin(ang);
}

// ---------------- fp32 -> fp16 convert -------------------------------------------
__global__ void convert_hi_fp16(const float2* __restrict__ s, __half2* __restrict__ hi, int n2) {
    int i = blockIdx.x * 256 + threadIdx.x;
    if (i >= n2) return;
    float2 v = s[i];
    hi[i] = __floats2half2_rn(v.x, v.y);
}

// ---------------- RoPE + head split (q/k only; q scaled by 1/sqrt(HD)*log2e) -----
#define QSCALE (0.08838834764831845f * 1.4426950408889634f)
__global__ void __launch_bounds__(256)
rope_split2_kernel() {
    int t0 = blockIdx.x * 32;
    int h = blockIdx.y;
    int b = blockIdx.z;
    int tid = threadIdx.x;
    int tt = tid >> 3;
    int pb = (tid & 7) * 8;
    int t = t0 + tt;
    int bh = b * NH + h;
    const __half* base = g_qkvh + (size_t)(b * TSEQ + t) * QKV_COLS;

    union U8 { __half h[8]; uint4 u[1]; };
    U8 qo1, qo2, kh1, kh2;
#pragma unroll
    for (int j = 0; j < 8; j++) {
        int d = pb + j;
        float c = g_cos[t * 64 + d];
        float s = g_sin[t * 64 + d];
        float q1 = __half2float(base[h * HD + d]);
        float q2 = __half2float(base[h * HD + d + 64]);
        float k1 = __half2float(base[DM + h * HD + d]);
        float k2 = __half2float(base[DM + h * HD + d + 64]);
        qo1.h[j] = __float2half_rn((q1 * c - q2 * s) * QSCALE);
        qo2.h[j] = __float2half_rn((q1 * s + q2 * c) * QSCALE);
        kh1.h[j] = __float2half_rn(k1 * c - k2 * s);
        kh2.h[j] = __float2half_rn(k1 * s + k2 * c);
    }
    size_t o = ((size_t)bh * TSEQ + t) * HD + pb;
    *(uint4*)(g_qh + o)      = qo1.u[0];
    *(uint4*)(g_qh + o + 64) = qo2.u[0];
    *(uint4*)(g_kh + o)      = kh1.u[0];
    *(uint4*)(g_kh + o + 64) = kh2.u[0];
}

// ---------------- HMMA fp16 GEMM (hi x hi), K64 2-stage, 64x32 warp tiles --------
#define GROW 72
#define GTILE_B (128 * GROW * 2)          // 18432 bytes
#define GSTAGE_B (2 * GTILE_B)            // 36864 bytes (Ah, Bh)
#define G_SMEM_TOTAL (2 * GSTAGE_B)       // 73728 bytes, 2 stages

__device__ __forceinline__ void ld_tile64(uint32_t dst, const __half* g, int ldK) {
#pragma unroll
    for (int r = 0; r < 4; r++) {
        int idx = threadIdx.x + r * 256;
        int row = idx >> 3, c = idx & 7;
        cpa16(dst + (row * GROW + c * 8) * 2, g + (size_t)row * ldK + c * 8);
    }
}

template <bool HALF_OUT>
__global__ void __launch_bounds__(256, 2)
gemm_fp16_1t(const __half* __restrict__ Ah, const __half* __restrict__ Bhi,
             const float* __restrict__ bias, void* __restrict__ Cv,
             int M, int N, int K) {
    extern __shared__ __align__(128) char sm[];
    uint32_t sb = smem_u32(sm);
    int tid = threadIdx.x, wid = tid >> 5, lane = tid & 31;
    int wm = wid & 1, wn = wid >> 1;
    int bm = blockIdx.y * 128, bn = blockIdx.x * 128;

    const __half* Ap = Ah  + (size_t)bm * K;
    const __half* Bh = Bhi + (size_t)bn * K;

    float acc[4][4][4];
#pragma unroll
    for (int i = 0; i < 4; i++)
#pragma unroll
        for (int j = 0; j < 4; j++)
#pragma unroll
            for (int k = 0; k < 4; k++) acc[i][j][k] = 0.f;

    int nc = K / 64;
#pragma unroll
    for (int s = 0; s < 2; s++) {
        uint32_t st = sb + s * GSTAGE_B;
        ld_tile64(st + 0 * GTILE_B, Ap + s * 64, K);
        ld_tile64(st + 1 * GTILE_B, Bh + s * 64, K);
        asm volatile("cp.async.commit_group;" ::: "memory");
    }

    int lrow = lane & 15;
    int lcol8 = (lane >> 4) * 8;

    for (int i = 0; i < nc; i++) {
        if (i == nc - 1) asm volatile("cp.async.wait_group 0;" ::: "memory");
        else             asm volatile("cp.async.wait_group 1;" ::: "memory");
        __syncthreads();

        uint32_t st = sb + (uint32_t)(i & 1) * GSTAGE_B;
        uint32_t sA = st, sBh = st + GTILE_B;

#pragma unroll
        for (int ks = 0; ks < 4; ks++) {
            int kc = ks * 16 + lcol8;
            uint32_t a[4][4], bh[2][4];
#pragma unroll
            for (int mi = 0; mi < 4; mi++) {
                int r = wm * 64 + mi * 16 + lrow;
                ldm_x4(a[mi], sA + (r * GROW + kc) * 2);
            }
#pragma unroll
            for (int nb = 0; nb < 2; nb++) {
                int r = wn * 32 + nb * 16 + lrow;
                ldm_x4(bh[nb], sBh + (r * GROW + kc) * 2);
            }
#pragma unroll
            for (int mi = 0; mi < 4; mi++)
#pragma unroll
                for (int nb = 0; nb < 2; nb++) {
                    mma16816h(acc[mi][2 * nb + 0], a[mi], bh[nb][0], bh[nb][2]);
                    mma16816h(acc[mi][2 * nb + 1], a[mi], bh[nb][1], bh[nb][3]);
                }
        }
        __syncthreads();
        if (i + 2 < nc) {
            int k0 = (i + 2) * 64;
            ld_tile64(st + 0 * GTILE_B, Ap + k0, K);
            ld_tile64(st + 1 * GTILE_B, Bh + k0, K);
            asm volatile("cp.async.commit_group;" ::: "memory");
        }
    }

    int qrow = lane >> 2, qcol = (lane & 3) * 2;
#pragma unroll
    for (int mi = 0; mi < 4; mi++) {
#pragma unroll
        for (int ni = 0; ni < 4; ni++) {
            int c = bn + wn * 32 + ni * 8 + qcol;
            float b0 = bias[c], b1 = bias[c + 1];
            int r0 = bm + wm * 64 + mi * 16 + qrow;
            if (HALF_OUT) {
                __half* C = (__half*)Cv;
                *(uint32_t*)(C + (size_t)r0 * N + c) =
                    packh(acc[mi][ni][0] + b0, acc[mi][ni][1] + b1);
                *(uint32_t*)(C + (size_t)(r0 + 8) * N + c) =
                    packh(acc[mi][ni][2] + b0, acc[mi][ni][3] + b1);
            } else {
                float* C = (float*)Cv;
                *(float2*)(C + (size_t)r0 * N + c) =
                    make_float2(acc[mi][ni][0] + b0, acc[mi][ni][1] + b1);
                *(float2*)(C + (size_t)(r0 + 8) * N + c) =
                    make_float2(acc[mi][ni][2] + b0, acc[mi][ni][3] + b1);
            }
        }
    }
}

// ---------------- HMMA flash attention (causal); V via ldmatrix.trans ------------
#define ABM 128
#define ABN 64
#define QSTR 136
#define KSTR 136
#define VSTR 136
#define KV_KH_B (ABN * KSTR * 2)                // 17408
#define KV_V_B  (ABN * VSTR * 2)                // 17408 (V tile [64 t][128 d] padded)
#define KV_STAGE_B (KV_KH_B + KV_V_B)           // 34816
#define SM_Q  0
#define SM_KV (ABM * QSTR * 2)                  // 34816
#define ATT_SMEM (SM_KV + 2 * KV_STAGE_B)       // 104448  -> 2 CTAs/SM

__device__ __forceinline__ void ld_kv(uint32_t stage_base, int bh, int kb) {
    const __half* Kh = g_kh + ((size_t)bh * TSEQ + kb * ABN) * HD;
#pragma unroll
    for (int i = 0; i < 4; i++) {
        int idx = threadIdx.x + i * 256;
        int row = idx >> 4, c = idx & 15;
        cpa16(stage_base + (row * KSTR + c * 8) * 2, Kh + (size_t)row * HD + c * 8);
    }
    // V straight from qkv output: token rows, v-head columns (no preprocessing)
    int b = bh >> 4, h = bh & 15;
    const __half* V = g_qkvh + (size_t)(b * TSEQ + kb * ABN) * QKV_COLS + 2 * DM + h * HD;
#pragma unroll
    for (int i = 0; i < 4; i++) {
        int idx = threadIdx.x + i * 256;
        int row = idx >> 4, c = idx & 15;
        cpa16(stage_base + KV_KH_B + (row * VSTR + c * 8) * 2,
              V + (size_t)row * QKV_COLS + c * 8);
    }
    asm volatile("cp.async.commit_group;" ::: "memory");
}

__global__ void __launch_bounds__(256, 2)
attn_mma_kernel() {
    extern __shared__ __align__(128) char smA[];
    uint32_t sb = smem_u32(smA);
    int tid = threadIdx.x, wid = tid >> 5, lane = tid & 31;
    int qb = (gridDim.x - 1) - blockIdx.x;      // heavy CTAs launch first
    int bh = blockIdx.y;
    int lrow = lane & 15;
    int lcol8 = (lane >> 4) * 8;
    int qrow = lane >> 2, qcol = (lane & 3) * 2;
    int nkb = 2 * qb + 2;

    // ---- prologue: Q, KV0, KV1 ----
    {
        const __half* Q = g_qh + ((size_t)bh * TSEQ + qb * ABM) * HD;
#pragma unroll
        for (int i = 0; i < 8; i++) {
            int idx = tid + i * 256;
            int row = idx >> 4, c = idx & 15;
            cpa16(sb + SM_Q + (row * QSTR + c * 8) * 2, Q + (size_t)row * HD + c * 8);
        }
        asm volatile("cp.async.commit_group;" ::: "memory");
    }
    ld_kv(sb + SM_KV, bh, 0);
    if (nkb > 1) ld_kv(sb + SM_KV + KV_STAGE_B, bh, 1);

    float o[16][4];
#pragma unroll
    for (int i = 0; i < 16; i++)
#pragma unroll
        for (int j = 0; j < 4; j++) o[i][j] = 0.f;
    float m0 = -1e30f, m1 = -1e30f, l0 = 0.f, l1 = 0.f;

    for (int kb = 0; kb < nkb; kb++) {
        if (kb + 1 < nkb) asm volatile("cp.async.wait_group 1;" ::: "memory");
        else              asm volatile("cp.async.wait_group 0;" ::: "memory");
        __syncthreads();

        uint32_t skv = sb + SM_KV + (uint32_t)(kb & 1) * KV_STAGE_B;
        uint32_t sKH = skv, sV = skv + KV_KH_B;

        // ---- S = Q K^T (logits in log2 units: q pre-scaled by log2e/sqrt(HD)) ----
        float s[8][4];
#pragma unroll
        for (int i = 0; i < 8; i++)
#pragma unroll
            for (int j = 0; j < 4; j++) s[i][j] = 0.f;
#pragma unroll
        for (int kc = 0; kc < 8; kc++) {
            uint32_t a[4];
            ldm_x4(a, sb + SM_Q + ((wid * 16 + lrow) * QSTR + kc * 16 + lcol8) * 2);
#pragma unroll
            for (int nb = 0; nb < 4; nb++) {
                uint32_t bhh[4];
                ldm_x4(bhh, sKH + ((nb * 16 + lrow) * KSTR + kc * 16 + lcol8) * 2);
                mma16816h(s[2 * nb + 0], a, bhh[0], bhh[2]);
                mma16816h(s[2 * nb + 1], a, bhh[1], bhh[3]);
            }
        }

        // ---- causal mask ----
        if (kb >= 2 * qb) {
            int rg = qb * ABM + wid * 16 + qrow;
#pragma unroll
            for (int nb = 0; nb < 8; nb++) {
#pragma unroll
                for (int e = 0; e < 2; e++) {
                    int col = kb * ABN + nb * 8 + qcol + e;
                    if (col > rg)     s[nb][e]     = -1e30f;
                    if (col > rg + 8) s[nb][2 + e] = -1e30f;
                }
            }
        }

        // ---- online softmax (base-2) ----
        float mx0 = -1e30f, mx1 = -1e30f;
#pragma unroll
        for (int nb = 0; nb < 8; nb++) {
            mx0 = fmaxf(mx0, fmaxf(s[nb][0], s[nb][1]));
            mx1 = fmaxf(mx1, fmaxf(s[nb][2], s[nb][3]));
        }
        mx0 = fmaxf(mx0, __shfl_xor_sync(0xffffffffu, mx0, 1));
        mx0 = fmaxf(mx0, __shfl_xor_sync(0xffffffffu, mx0, 2));
        mx1 = fmaxf(mx1, __shfl_xor_sync(0xffffffffu, mx1, 1));
        mx1 = fmaxf(mx1, __shfl_xor_sync(0xffffffffu, mx1, 2));
        float mn0 = fmaxf(m0, mx0), mn1 = fmaxf(m1, mx1);
        float a0 = exp2f(m0 - mn0), a1 = exp2f(m1 - mn1);
        float sum0 = 0.f, sum1 = 0.f;
#pragma unroll
        for (int nb = 0; nb < 8; nb++) {
            s[nb][0] = exp2f(s[nb][0] - mn0); sum0 += s[nb][0];
            s[nb][1] = exp2f(s[nb][1] - mn0); sum0 += s[nb][1];
            s[nb][2] = exp2f(s[nb][2] - mn1); sum1 += s[nb][2];
            s[nb][3] = exp2f(s[nb][3] - mn1); sum1 += s[nb][3];
        }
        sum0 += __shfl_xor_sync(0xffffffffu, sum0, 1);
        sum0 += __shfl_xor_sync(0xffffffffu, sum0, 2);
        sum1 += __shfl_xor_sync(0xffffffffu, sum1, 1);
        sum1 += __shfl_xor_sync(0xffffffffu, sum1, 2);
        l0 = l0 * a0 + sum0; l1 = l1 * a1 + sum1;
        m0 = mn0; m1 = mn1;
#pragma unroll
        for (int nb = 0; nb < 16; nb++) {
            o[nb][0] *= a0; o[nb][1] *= a0;
            o[nb][2] *= a1; o[nb][3] *= a1;
        }

        // ---- O += P @ V (V tile [t][d], B frags via ldmatrix.trans) ----
#pragma unroll
        for (int kk = 0; kk < 4; kk++) {
            uint32_t pah[4];
            pah[0] = packh(s[2 * kk][0],     s[2 * kk][1]);
            pah[1] = packh(s[2 * kk][2],     s[2 * kk][3]);
            pah[2] = packh(s[2 * kk + 1][0], s[2 * kk + 1][1]);
            pah[3] = packh(s[2 * kk + 1][2], s[2 * kk + 1][3]);
#pragma unroll
            for (int blk = 0; blk < 8; blk++) {
                uint32_t vb[4];
                ldm_x4t(vb, sV + ((kk * 16 + lrow) * VSTR + blk * 16 + lcol8) * 2);
                mma16816h(o[2 * blk + 0], pah, vb[0], vb[1]);
                mma16816h(o[2 * blk + 1], pah, vb[2], vb[3]);
            }
        }
        __syncthreads();

        if (kb + 2 < nkb) ld_kv(sb + SM_KV + (uint32_t)(kb & 1) * KV_STAGE_B, bh, kb + 2);
    }

    // ---- epilogue: normalize and write ctx directly as fp16 ----
    float inv0 = 1.0f / l0, inv1 = 1.0f / l1;
    int b = bh >> 4, h = bh & 15;
    int r0 = qb * ABM + wid * 16 + qrow;
    __half* base0 = g_ch + ((size_t)(b * TSEQ + r0)) * DM + h * HD + qcol;
    __half* base1 = g_ch + ((size_t)(b * TSEQ + r0 + 8)) * DM + h * HD + qcol;
#pragma unroll
    for (int nb = 0; nb < 16; nb++) {
        *(uint32_t*)(base0 + nb * 8) = packh(o[nb][0] * inv0, o[nb][1] * inv0);
        *(uint32_t*)(base1 + nb * 8) = packh(o[nb][2] * inv1, o[nb][3] * inv1);
    }
}

// ---------------- launcher --------------------------------------------------------
extern "C" void kernel_launch(void* const* d_in, const int* in_sizes, int n_in,
                              void* d_out, int out_size) {
    const float* x    = (const float*)d_in[0];
    const float* Wqkv = (const float*)d_in[1];
    const float* bqkv = (const float*)d_in[2];
    const float* Wo   = (const float*)d_in[3];
    const float* bo   = (const float*)d_in[4];
    float* out = (float*)d_out;

    __half *qkvh, *xh, *wqh, *woh, *ch;
    cudaGetSymbolAddress((void**)&qkvh, g_qkvh);
    cudaGetSymbolAddress((void**)&xh, g_xh);
    cudaGetSymbolAddress((void**)&wqh, g_wqkvh);
    cudaGetSymbolAddress((void**)&woh, g_woh);
    cudaGetSymbolAddress((void**)&ch, g_ch);

    cudaFuncSetAttribute(gemm_fp16_1t<true>,
                         cudaFuncAttributeMaxDynamicSharedMemorySize, G_SMEM_TOTAL);
    cudaFuncSetAttribute(gemm_fp16_1t<false>,
                         cudaFuncAttributeMaxDynamicSharedMemorySize, G_SMEM_TOTAL);
    cudaFuncSetAttribute(attn_mma_kernel,
                         cudaFuncAttributeMaxDynamicSharedMemorySize, ATT_SMEM);

    // 1) RoPE table
    rope_table_kernel<<<(TSEQ * (HD / 2) + 255) / 256, 256>>>();

    // 2) converts: x, Wqkv -> fp16 hi
    {
        int n2 = (NTOK * DM) / 2;
        convert_hi_fp16<<<(n2 + 255) / 256, 256>>>((const float2*)x, (__half2*)xh, n2);
        n2 = (QKV_COLS * DM) / 2;
        convert_hi_fp16<<<(n2 + 255) / 256, 256>>>((const float2*)Wqkv, (__half2*)wqh, n2);
    }

    // 3) QKV projection (fp16 HMMA, 2-stage, fp16 output)
    {
        dim3 grid(QKV_COLS / 128, NTOK / 128);
        gemm_fp16_1t<true><<<grid, 256, G_SMEM_TOTAL>>>(xh, wqh, bqkv, qkvh,
                                                        NTOK, QKV_COLS, DM);
    }

    // 4) RoPE + head split (q/k only; V consumed in place by attention)
    {
        dim3 grid(TSEQ / 32, NH, BB);
        rope_split2_kernel<<<grid, 256>>>();
    }

    // 5) causal flash attention (fp16; V via ldmatrix.trans from qkv buffer)
    {
        dim3 grid(TSEQ / ABM, BB * NH);
        attn_mma_kernel<<<grid, 256, ATT_SMEM>>>();
    }

    // 6) convert: Wo -> fp16 hi
    {
        int n2 = (DM * DM) / 2;
        convert_hi_fp16<<<(n2 + 255) / 256, 256>>>((const float2*)Wo, (__half2*)woh, n2);
    }

    // 7) output projection (fp16 HMMA, fp32 output)
    {
        dim3 grid(DM / 128, NTOK / 128);
        gemm_fp16_1t<false><<<grid, 256, G_SMEM_TOTAL>>>(ch, woh, bo, out,
                                                         NTOK, DM, DM);
    }
}

// round 17
// speedup vs baseline: 1.0692x; 1.0166x over previous
#include <cuda_runtime.h>
#include <cuda_fp16.h>
#include <math.h>
#include <stdint.h>

#define NH 16
#define HD 128
#define TSEQ 2048
#define BB 2
#define DM 2048
#define NTOK (BB * TSEQ)          // 4096
#define QKV_COLS (3 * DM)         // 6144

// ---------------- scratch (device globals: no allocation allowed) ------------
__device__ __half g_qkvh[(size_t)NTOK * QKV_COLS];   // fp16 qkv (V read in-place)
__device__ float g_cos[TSEQ * (HD / 2)];
__device__ float g_sin[TSEQ * (HD / 2)];
__device__ __half g_xh[(size_t)NTOK * DM];
__device__ __half g_wqkvh[(size_t)QKV_COLS * DM];
__device__ __half g_woh[(size_t)DM * DM];
__device__ __half g_ch[(size_t)NTOK * DM];    // attention output, fp16
#define BH_T_HD ((size_t)BB * NH * TSEQ * HD)
__device__ __half g_qh[BH_T_HD];
__device__ __half g_kh[BH_T_HD];

// ---------------- helpers ------------------------------------------------------
__device__ __forceinline__ uint32_t smem_u32(const void* p) {
    uint32_t a;
    asm("{ .reg .u64 t; cvta.to.shared.u64 t, %1; cvt.u32.u64 %0, t; }"
        : "=r"(a) : "l"(p));
    return a;
}
__device__ __forceinline__ void cpa16(uint32_t dst, const void* src) {
    asm volatile("cp.async.cg.shared.global [%0], [%1], 16;" :: "r"(dst), "l"(src));
}
__device__ __forceinline__ void ldm_x4(uint32_t* r, uint32_t addr) {
    asm volatile("ldmatrix.sync.aligned.m8n8.x4.shared.b16 {%0,%1,%2,%3}, [%4];"
                 : "=r"(r[0]), "=r"(r[1]), "=r"(r[2]), "=r"(r[3]) : "r"(addr));
}
__device__ __forceinline__ void ldm_x4t(uint32_t* r, uint32_t addr) {
    asm volatile("ldmatrix.sync.aligned.m8n8.x4.trans.shared.b16 {%0,%1,%2,%3}, [%4];"
                 : "=r"(r[0]), "=r"(r[1]), "=r"(r[2]), "=r"(r[3]) : "r"(addr));
}
__device__ __forceinline__ void mma16816h(float* d, const uint32_t* a, uint32_t b0, uint32_t b1) {
    asm volatile(
        "mma.sync.aligned.m16n8k16.row.col.f32.f16.f16.f32 "
        "{%0,%1,%2,%3}, {%4,%5,%6,%7}, {%8,%9}, {%0,%1,%2,%3};"
        : "+f"(d[0]), "+f"(d[1]), "+f"(d[2]), "+f"(d[3])
        : "r"(a[0]), "r"(a[1]), "r"(a[2]), "r"(a[3]), "r"(b0), "r"(b1));
}
__device__ __forceinline__ uint32_t packh(float p0, float p1) {
    uint32_t r;
    asm("cvt.rn.f16x2.f32 %0, %1, %2;" : "=r"(r) : "f"(p1), "f"(p0));
    return r;
}

// ---------------- fused prep: x/Wqkv/Wo fp16 converts + RoPE table ---------------
// block ranges: [0,4096) x | [4096,10240) Wqkv | [10240,12288) Wo | [12288,12800) table
#define PREP_X_BLKS    4096
#define PREP_WQ_BLKS   6144
#define PREP_WO_BLKS   2048
#define PREP_TBL_BLKS  512
#define PREP_BLKS (PREP_X_BLKS + PREP_WQ_BLKS + PREP_WO_BLKS + PREP_TBL_BLKS)

__device__ __forceinline__ void conv4(const float4* __restrict__ s,
                                      uint4* __restrict__ d, size_t tIdx) {
    float4 a = s[2 * tIdx], b = s[2 * tIdx + 1];
    uint4 r;
    r.x = packh(a.x, a.y); r.y = packh(a.z, a.w);
    r.z = packh(b.x, b.y); r.w = packh(b.z, b.w);
    d[tIdx] = r;
}

__global__ void __launch_bounds__(256)
prep_kernel(const float4* __restrict__ x, const float4* __restrict__ wqkv,
            const float4* __restrict__ wo) {
    int bid = blockIdx.x;
    if (bid < PREP_X_BLKS) {
        conv4(x, (uint4*)g_xh, (size_t)bid * 256 + threadIdx.x);
    } else if (bid < PREP_X_BLKS + PREP_WQ_BLKS) {
        conv4(wqkv, (uint4*)g_wqkvh,
              (size_t)(bid - PREP_X_BLKS) * 256 + threadIdx.x);
    } else if (bid < PREP_X_BLKS + PREP_WQ_BLKS + PREP_WO_BLKS) {
        conv4(wo, (uint4*)g_woh,
              (size_t)(bid - PREP_X_BLKS - PREP_WQ_BLKS) * 256 + threadIdx.x);
    } else {
        int idx = (bid - PREP_X_BLKS - PREP_WQ_BLKS - PREP_WO_BLKS) * 256 + threadIdx.x;
        int t = idx >> 6;              // / (HD/2)
        int i = idx & 63;
        double inv = exp(-log(10000.0) * (double)(2 * i) / (double)HD);
        double ang = (double)t * inv;
        g_cos[idx] = (float)cos(ang);
        g_sin[idx] = (float)sin(ang);
    }
}

// ---------------- RoPE + head split (q/k only; q scaled by log2e/sqrt(HD)) -------
#define QSCALE (0.08838834764831845f * 1.4426950408889634f)
__global__ void __launch_bounds__(256)
rope_split2_kernel() {
    int t0 = blockIdx.x * 32;
    int h = blockIdx.y;
    int b = blockIdx.z;
    int tid = threadIdx.x;
    int tt = tid >> 3;
    int pb = (tid & 7) * 8;
    int t = t0 + tt;
    int bh = b * NH + h;
    const __half* base = g_qkvh + (size_t)(b * TSEQ + t) * QKV_COLS;

    union U8 { __half h[8]; uint4 u[1]; };
    U8 qo1, qo2, kh1, kh2;
#pragma unroll
    for (int j = 0; j < 8; j++) {
        int d = pb + j;
        float c = g_cos[t * 64 + d];
        float s = g_sin[t * 64 + d];
        float q1 = __half2float(base[h * HD + d]);
        float q2 = __half2float(base[h * HD + d + 64]);
        float k1 = __half2float(base[DM + h * HD + d]);
        float k2 = __half2float(base[DM + h * HD + d + 64]);
        qo1.h[j] = __float2half_rn((q1 * c - q2 * s) * QSCALE);
        qo2.h[j] = __float2half_rn((q1 * s + q2 * c) * QSCALE);
        kh1.h[j] = __float2half_rn(k1 * c - k2 * s);
        kh2.h[j] = __float2half_rn(k1 * s + k2 * c);
    }
    size_t o = ((size_t)bh * TSEQ + t) * HD + pb;
    *(uint4*)(g_qh + o)      = qo1.u[0];
    *(uint4*)(g_qh + o + 64) = qo2.u[0];
    *(uint4*)(g_kh + o)      = kh1.u[0];
    *(uint4*)(g_kh + o + 64) = kh2.u[0];
}

// ---------------- HMMA fp16 GEMM (hi x hi), K64 2-stage, 64x32 warp tiles --------
#define GROW 72
#define GTILE_B (128 * GROW * 2)          // 18432 bytes
#define GSTAGE_B (2 * GTILE_B)            // 36864 bytes (Ah, Bh)
#define G_SMEM_TOTAL (2 * GSTAGE_B)       // 73728 bytes, 2 stages

__device__ __forceinline__ void ld_tile64(uint32_t dst, const __half* g, int ldK) {
#pragma unroll
    for (int r = 0; r < 4; r++) {
        int idx = threadIdx.x + r * 256;
        int row = idx >> 3, c = idx & 7;
        cpa16(dst + (row * GROW + c * 8) * 2, g + (size_t)row * ldK + c * 8);
    }
}

template <bool HALF_OUT>
__global__ void __launch_bounds__(256, 2)
gemm_fp16_1t(const __half* __restrict__ Ah, const __half* __restrict__ Bhi,
             const float* __restrict__ bias, void* __restrict__ Cv,
             int M, int N, int K) {
    extern __shared__ __align__(128) char sm[];
    uint32_t sb = smem_u32(sm);
    int tid = threadIdx.x, wid = tid >> 5, lane = tid & 31;
    int wm = wid & 1, wn = wid >> 1;
    int bm = blockIdx.y * 128, bn = blockIdx.x * 128;

    const __half* Ap = Ah  + (size_t)bm * K;
    const __half* Bh = Bhi + (size_t)bn * K;

    float acc[4][4][4];
#pragma unroll
    for (int i = 0; i < 4; i++)
#pragma unroll
        for (int j = 0; j < 4; j++)
#pragma unroll
            for (int k = 0; k < 4; k++) acc[i][j][k] = 0.f;

    int nc = K / 64;
#pragma unroll
    for (int s = 0; s < 2; s++) {
        uint32_t st = sb + s * GSTAGE_B;
        ld_tile64(st + 0 * GTILE_B, Ap + s * 64, K);
        ld_tile64(st + 1 * GTILE_B, Bh + s * 64, K);
        asm volatile("cp.async.commit_group;" ::: "memory");
    }

    int lrow = lane & 15;
    int lcol8 = (lane >> 4) * 8;

    for (int i = 0; i < nc; i++) {
        if (i == nc - 1) asm volatile("cp.async.wait_group 0;" ::: "memory");
        else             asm volatile("cp.async.wait_group 1;" ::: "memory");
        __syncthreads();

        uint32_t st = sb + (uint32_t)(i & 1) * GSTAGE_B;
        uint32_t sA = st, sBh = st + GTILE_B;

#pragma unroll
        for (int ks = 0; ks < 4; ks++) {
            int kc = ks * 16 + lcol8;
            uint32_t a[4][4], bh[2][4];
#pragma unroll
            for (int mi = 0; mi < 4; mi++) {
                int r = wm * 64 + mi * 16 + lrow;
                ldm_x4(a[mi], sA + (r * GROW + kc) * 2);
            }
#pragma unroll
            for (int nb = 0; nb < 2; nb++) {
                int r = wn * 32 + nb * 16 + lrow;
                ldm_x4(bh[nb], sBh + (r * GROW + kc) * 2);
            }
#pragma unroll
            for (int mi = 0; mi < 4; mi++)
#pragma unroll
                for (int nb = 0; nb < 2; nb++) {
                    mma16816h(acc[mi][2 * nb + 0], a[mi], bh[nb][0], bh[nb][2]);
                    mma16816h(acc[mi][2 * nb + 1], a[mi], bh[nb][1], bh[nb][3]);
                }
        }
        __syncthreads();
        if (i + 2 < nc) {
            int k0 = (i + 2) * 64;
            ld_tile64(st + 0 * GTILE_B, Ap + k0, K);
            ld_tile64(st + 1 * GTILE_B, Bh + k0, K);
            asm volatile("cp.async.commit_group;" ::: "memory");
        }
    }

    int qrow = lane >> 2, qcol = (lane & 3) * 2;
#pragma unroll
    for (int mi = 0; mi < 4; mi++) {
#pragma unroll
        for (int ni = 0; ni < 4; ni++) {
            int c = bn + wn * 32 + ni * 8 + qcol;
            float b0 = bias[c], b1 = bias[c + 1];
            int r0 = bm + wm * 64 + mi * 16 + qrow;
            if (HALF_OUT) {
                __half* C = (__half*)Cv;
                *(uint32_t*)(C + (size_t)r0 * N + c) =
                    packh(acc[mi][ni][0] + b0, acc[mi][ni][1] + b1);
                *(uint32_t*)(C + (size_t)(r0 + 8) * N + c) =
                    packh(acc[mi][ni][2] + b0, acc[mi][ni][3] + b1);
            } else {
                float* C = (float*)Cv;
                *(float2*)(C + (size_t)r0 * N + c) =
                    make_float2(acc[mi][ni][0] + b0, acc[mi][ni][1] + b1);
                *(float2*)(C + (size_t)(r0 + 8) * N + c) =
                    make_float2(acc[mi][ni][2] + b0, acc[mi][ni][3] + b1);
            }
        }
    }
}

// ---------------- HMMA flash attention (causal); V via ldmatrix.trans ------------
#define ABM 128
#define ABN 64
#define QSTR 136
#define KSTR 136
#define VSTR 136
#define KV_KH_B (ABN * KSTR * 2)                // 17408
#define KV_V_B  (ABN * VSTR * 2)                // 17408 (V tile [64 t][128 d])
#define KV_STAGE_B (KV_KH_B + KV_V_B)           // 34816
#define SM_Q  0
#define SM_KV (ABM * QSTR * 2)                  // 34816
#define ATT_SMEM (SM_KV + 2 * KV_STAGE_B)       // 104448  -> 2 CTAs/SM

__device__ __forceinline__ void ld_kv(uint32_t stage_base, int bh, int kb) {
    const __half* Kh = g_kh + ((size_t)bh * TSEQ + kb * ABN) * HD;
#pragma unroll
    for (int i = 0; i < 4; i++) {
        int idx = threadIdx.x + i * 256;
        int row = idx >> 4, c = idx & 15;
        cpa16(stage_base + (row * KSTR + c * 8) * 2, Kh + (size_t)row * HD + c * 8);
    }
    int b = bh >> 4, h = bh & 15;
    const __half* V = g_qkvh + (size_t)(b * TSEQ + kb * ABN) * QKV_COLS + 2 * DM + h * HD;
#pragma unroll
    for (int i = 0; i < 4; i++) {
        int idx = threadIdx.x + i * 256;
        int row = idx >> 4, c = idx & 15;
        cpa16(stage_base + KV_KH_B + (row * VSTR + c * 8) * 2,
              V + (size_t)row * QKV_COLS + c * 8);
    }
    asm volatile("cp.async.commit_group;" ::: "memory");
}

__global__ void __launch_bounds__(256, 2)
attn_mma_kernel() {
    extern __shared__ __align__(128) char smA[];
    uint32_t sb = smem_u32(smA);
    int tid = threadIdx.x, wid = tid >> 5, lane = tid & 31;
    int qb = (gridDim.x - 1) - blockIdx.x;      // heavy CTAs launch first
    int bh = blockIdx.y;
    int lrow = lane & 15;
    int lcol8 = (lane >> 4) * 8;
    int qrow = lane >> 2, qcol = (lane & 3) * 2;
    int nkb = 2 * qb + 2;

    {
        const __half* Q = g_qh + ((size_t)bh * TSEQ + qb * ABM) * HD;
#pragma unroll
        for (int i = 0; i < 8; i++) {
            int idx = tid + i * 256;
            int row = idx >> 4, c = idx & 15;
            cpa16(sb + SM_Q + (row * QSTR + c * 8) * 2, Q + (size_t)row * HD + c * 8);
        }
        asm volatile("cp.async.commit_group;" ::: "memory");
    }
    ld_kv(sb + SM_KV, bh, 0);
    if (nkb > 1) ld_kv(sb + SM_KV + KV_STAGE_B, bh, 1);

    float o[16][4];
#pragma unroll
    for (int i = 0; i < 16; i++)
#pragma unroll
        for (int j = 0; j < 4; j++) o[i][j] = 0.f;
    float m0 = -1e30f, m1 = -1e30f, l0 = 0.f, l1 = 0.f;

    for (int kb = 0; kb < nkb; kb++) {
        if (kb + 1 < nkb) asm volatile("cp.async.wait_group 1;" ::: "memory");
        else              asm volatile("cp.async.wait_group 0;" ::: "memory");
        __syncthreads();

        uint32_t skv = sb + SM_KV + (uint32_t)(kb & 1) * KV_STAGE_B;
        uint32_t sKH = skv, sV = skv + KV_KH_B;

        float s[8][4];
#pragma unroll
        for (int i = 0; i < 8; i++)
#pragma unroll
            for (int j = 0; j < 4; j++) s[i][j] = 0.f;
#pragma unroll
        for (int kc = 0; kc < 8; kc++) {
            uint32_t a[4];
            ldm_x4(a, sb + SM_Q + ((wid * 16 + lrow) * QSTR + kc * 16 + lcol8) * 2);
#pragma unroll
            for (int nb = 0; nb < 4; nb++) {
                uint32_t bhh[4];
                ldm_x4(bhh, sKH + ((nb * 16 + lrow) * KSTR + kc * 16 + lcol8) * 2);
                mma16816h(s[2 * nb + 0], a, bhh[0], bhh[2]);
                mma16816h(s[2 * nb + 1], a, bhh[1], bhh[3]);
            }
        }

        if (kb >= 2 * qb) {
            int rg = qb * ABM + wid * 16 + qrow;
#pragma unroll
            for (int nb = 0; nb < 8; nb++) {
#pragma unroll
                for (int e = 0; e < 2; e++) {
                    int col = kb * ABN + nb * 8 + qcol + e;
                    if (col > rg)     s[nb][e]     = -1e30f;
                    if (col > rg + 8) s[nb][2 + e] = -1e30f;
                }
            }
        }

        float mx0 = -1e30f, mx1 = -1e30f;
#pragma unroll
        for (int nb = 0; nb < 8; nb++) {
            mx0 = fmaxf(mx0, fmaxf(s[nb][0], s[nb][1]));
            mx1 = fmaxf(mx1, fmaxf(s[nb][2], s[nb][3]));
        }
        mx0 = fmaxf(mx0, __shfl_xor_sync(0xffffffffu, mx0, 1));
        mx0 = fmaxf(mx0, __shfl_xor_sync(0xffffffffu, mx0, 2));
        mx1 = fmaxf(mx1, __shfl_xor_sync(0xffffffffu, mx1, 1));
        mx1 = fmaxf(mx1, __shfl_xor_sync(0xffffffffu, mx1, 2));
        float mn0 = fmaxf(m0, mx0), mn1 = fmaxf(m1, mx1);
        float a0 = exp2f(m0 - mn0), a1 = exp2f(m1 - mn1);
        float sum0 = 0.f, sum1 = 0.f;
#pragma unroll
        for (int nb = 0; nb < 8; nb++) {
            s[nb][0] = exp2f(s[nb][0] - mn0); sum0 += s[nb][0];
            s[nb][1] = exp2f(s[nb][1] - mn0); sum0 += s[nb][1];
            s[nb][2] = exp2f(s[nb][2] - mn1); sum1 += s[nb][2];
            s[nb][3] = exp2f(s[nb][3] - mn1); sum1 += s[nb][3];
        }
        sum0 += __shfl_xor_sync(0xffffffffu, sum0, 1);
        sum0 += __shfl_xor_sync(0xffffffffu, sum0, 2);
        sum1 += __shfl_xor_sync(0xffffffffu, sum1, 1);
        sum1 += __shfl_xor_sync(0xffffffffu, sum1, 2);
        l0 = l0 * a0 + sum0; l1 = l1 * a1 + sum1;
        m0 = mn0; m1 = mn1;
#pragma unroll
        for (int nb = 0; nb < 16; nb++) {
            o[nb][0] *= a0; o[nb][1] *= a0;
            o[nb][2] *= a1; o[nb][3] *= a1;
        }

#pragma unroll
        for (int kk = 0; kk < 4; kk++) {
            uint32_t pah[4];
            pah[0] = packh(s[2 * kk][0],     s[2 * kk][1]);
            pah[1] = packh(s[2 * kk][2],     s[2 * kk][3]);
            pah[2] = packh(s[2 * kk + 1][0], s[2 * kk + 1][1]);
            pah[3] = packh(s[2 * kk + 1][2], s[2 * kk + 1][3]);
#pragma unroll
            for (int blk = 0; blk < 8; blk++) {
                uint32_t vb[4];
                ldm_x4t(vb, sV + ((kk * 16 + lrow) * VSTR + blk * 16 + lcol8) * 2);
                mma16816h(o[2 * blk + 0], pah, vb[0], vb[1]);
                mma16816h(o[2 * blk + 1], pah, vb[2], vb[3]);
            }
        }
        __syncthreads();

        if (kb + 2 < nkb) ld_kv(sb + SM_KV + (uint32_t)(kb & 1) * KV_STAGE_B, bh, kb + 2);
    }

    float inv0 = 1.0f / l0, inv1 = 1.0f / l1;
    int b = bh >> 4, h = bh & 15;
    int r0 = qb * ABM + wid * 16 + qrow;
    __half* base0 = g_ch + ((size_t)(b * TSEQ + r0)) * DM + h * HD + qcol;
    __half* base1 = g_ch + ((size_t)(b * TSEQ + r0 + 8)) * DM + h * HD + qcol;
#pragma unroll
    for (int nb = 0; nb < 16; nb++) {
        *(uint32_t*)(base0 + nb * 8) = packh(o[nb][0] * inv0, o[nb][1] * inv0);
        *(uint32_t*)(base1 + nb * 8) = packh(o[nb][2] * inv1, o[nb][3] * inv1);
    }
}

// ---------------- launcher --------------------------------------------------------
extern "C" void kernel_launch(void* const* d_in, const int* in_sizes, int n_in,
                              void* d_out, int out_size) {
    const float* x    = (const float*)d_in[0];
    const float* Wqkv = (const float*)d_in[1];
    const float* bqkv = (const float*)d_in[2];
    const float* Wo   = (const float*)d_in[3];
    const float* bo   = (const float*)d_in[4];
    float* out = (float*)d_out;

    __half *qkvh, *xh, *wqh, *woh, *ch;
    cudaGetSymbolAddress((void**)&qkvh, g_qkvh);
    cudaGetSymbolAddress((void**)&xh, g_xh);
    cudaGetSymbolAddress((void**)&wqh, g_wqkvh);
    cudaGetSymbolAddress((void**)&woh, g_woh);
    cudaGetSymbolAddress((void**)&ch, g_ch);

    cudaFuncSetAttribute(gemm_fp16_1t<true>,
                         cudaFuncAttributeMaxDynamicSharedMemorySize, G_SMEM_TOTAL);
    cudaFuncSetAttribute(gemm_fp16_1t<false>,
                         cudaFuncAttributeMaxDynamicSharedMemorySize, G_SMEM_TOTAL);
    cudaFuncSetAttribute(attn_mma_kernel,
                         cudaFuncAttributeMaxDynamicSharedMemorySize, ATT_SMEM);

    // 1) fused prep: x/Wqkv/Wo -> fp16 + RoPE table (one launch)
    prep_kernel<<<PREP_BLKS, 256>>>((const float4*)x, (const float4*)Wqkv,
                                    (const float4*)Wo);

    // 2) QKV projection (fp16 HMMA, 2-stage, fp16 output)
    {
        dim3 grid(QKV_COLS / 128, NTOK / 128);
        gemm_fp16_1t<true><<<grid, 256, G_SMEM_TOTAL>>>(xh, wqh, bqkv, qkvh,
                                                        NTOK, QKV_COLS, DM);
    }

    // 3) RoPE + head split (q/k only)
    {
        dim3 grid(TSEQ / 32, NH, BB);
        rope_split2_kernel<<<grid, 256>>>();
    }

    // 4) causal flash attention (fp16; V via ldmatrix.trans from qkv buffer)
    {
        dim3 grid(TSEQ / ABM, BB * NH);
        attn_mma_kernel<<<grid, 256, ATT_SMEM>>>();
    }

    // 5) output projection (fp16 HMMA, fp32 output)
    {
        dim3 grid(DM / 128, NTOK / 128);
        gemm_fp16_1t<false><<<grid, 256, G_SMEM_TOTAL>>>(ch, woh, bo, out,
                                                         NTOK, DM, DM);
    }
}